// round 4
// baseline (speedup 1.0000x reference)
#include <cuda_runtime.h>
#include <cuda_bf16.h>

// Problem constants: P=Q=3, M=N=127, DIM=3, SU=SV=256, B=16
#define PB    16
#define PDEG  3
#define PM    127
#define PL    132          // knot vector length
#define PS    256          // samples per direction
#define PNC   128          // control points per direction
#define PDIM  3
#define PEPS  1e-8f
#define RG    4            // rows per thread in rowsum kernel

// ---- device scratch (allocation-free) ----
__device__ float4 g_R[PB][PNC][PS];     // 8 MB rowsum scratch (L2-resident)

// ---------------------------------------------------------------------------
// Shared helper: normalize knots into sK (cumsum + rescale).
// Must be called by all threads of the block; leaves sK normalized, synced.
// ---------------------------------------------------------------------------
__device__ __forceinline__ void knots_to_sK(const float* __restrict__ knots,
                                            float* sK, int tid)
{
    if (tid < PL) {
        float x = knots[tid];
        sK[tid] = (x < 0.0f) ? 0.0001f : x;
    }
    __syncthreads();

    // warp 0: inclusive scan of 132 elems via per-lane chunks + shuffle scan
    if (tid < 32) {
        const int CH = 5;                       // 32*5 >= 132
        const int base = tid * CH;
        float vch[CH];
        float run = 0.0f;
        #pragma unroll
        for (int k = 0; k < CH; k++) {
            int i = base + k;
            float x = (i < PL) ? sK[i] : 0.0f;
            run += x;
            vch[k] = run;
        }
        float incl = run;
        #pragma unroll
        for (int off = 1; off < 32; off <<= 1) {
            float nb = __shfl_up_sync(0xffffffffu, incl, off);
            if (tid >= off) incl += nb;
        }
        float excl = incl - run;
        #pragma unroll
        for (int k = 0; k < CH; k++) {
            int i = base + k;
            if (i < PL) sK[i] = excl + vch[k];
        }
    }
    __syncthreads();

    const float k0  = sK[0];
    const float inv = 1.0f / (sK[PL - 1] - k0);
    __syncthreads();
    if (tid < PL) sK[tid] = (sK[tid] - k0) * inv;
    __syncthreads();
}

// span find (binary search + tie-walk, matches argmin semantics) + Cox-de Boor
__device__ __forceinline__ int basis_at(const float* sK, float t, float* Ni)
{
    int j;
    {
        const int cnt = PL - 2 * PDEG;          // 126
        int lo = 0, hi = cnt;
        while (lo < hi) {
            int mid = (lo + hi) >> 1;
            if (t - sK[PDEG + mid] > PEPS) lo = mid + 1;
            else hi = mid;
        }
        j = lo - 1;
        if (j < 0) j = 0;
        else {
            while (j > 0 && sK[PDEG + j - 1] == sK[PDEG + j]) j--;
        }
    }
    int span = j + PDEG;
    if (span < PDEG) span = PDEG;
    if (span > PM)   span = PM;

    Ni[0] = 1.0f; Ni[1] = 0.0f; Ni[2] = 0.0f; Ni[3] = 0.0f;
    #pragma unroll
    for (int k = 1; k <= PDEG; k++) {
        float saved = 0.0f;
        #pragma unroll
        for (int r = 0; r < PDEG; r++) {
            if (r >= k) break;
            float K1 = sK[span + r + 1];
            float K2 = sK[span + 1 - k + r];
            float denom = (K1 - t) + (t - K2);
            float temp = (denom == 0.0f) ? 0.0001f : __fdividef(Ni[r], denom);
            Ni[r] = saved + (K1 - t) * temp;
            saved = (t - K2) * temp;
        }
        Ni[k] = saved;
    }
    return span;
}

// ---------------------------------------------------------------------------
// Kernel 1: fused v-basis + rowsums.
// R[b][r][vv] = sum_q Nv[q][vv] * ctrl[b][r][iv+q][:]
// grid = B * (PNC/RG) = 512 blocks, blockDim = 256 (thread = vv).
// ---------------------------------------------------------------------------
__global__ void __launch_bounds__(PS)
surf_rowsum_kernel(const float* __restrict__ ctrl,
                   const float* __restrict__ knot_v,
                   const float* __restrict__ v)
{
    const int b     = blockIdx.x / (PNC / RG);
    const int rbase = (blockIdx.x % (PNC / RG)) * RG;
    const int vv    = threadIdx.x;

    __shared__ float sK[PL];
    knots_to_sK(knot_v + b * PL, sK, threadIdx.x);

    float nv[PDEG + 1];
    const int span = basis_at(sK, v[vv], nv);
    const int iv = span - PDEG;

    const float* base = ctrl + (((long)b * PNC) * PNC + iv) * PDIM;

    #pragma unroll
    for (int j = 0; j < RG; j++) {
        const float* row = base + (long)(rbase + j) * (PNC * PDIM);
        float s0 = 0.0f, s1 = 0.0f, s2 = 0.0f;
        #pragma unroll
        for (int q = 0; q <= PDEG; q++) {
            const float w = nv[q];
            s0 = fmaf(w, __ldg(row + q * PDIM + 0), s0);
            s1 = fmaf(w, __ldg(row + q * PDIM + 1), s1);
            s2 = fmaf(w, __ldg(row + q * PDIM + 2), s2);
        }
        g_R[b][rbase + j][vv] = make_float4(s0, s1, s2, 0.0f);
    }
}

// ---------------------------------------------------------------------------
// Kernel 2: fused u-basis + u-contraction.
// out[b][uu][vv] = sum_p Nu[p][uu] * R[b][iu+p][vv]
// blockDim = (256, 2), grid = B * PS/2 = 2048 blocks.
// ---------------------------------------------------------------------------
__global__ void __launch_bounds__(512)
surf_ucontract_kernel(const float* __restrict__ knot_u,
                      const float* __restrict__ u,
                      float* __restrict__ out)
{
    const int b   = blockIdx.x / (PS / 2);
    const int ug  = blockIdx.x % (PS / 2);
    const int tid = threadIdx.y * PS + threadIdx.x;

    __shared__ float sK[PL];
    __shared__ float s_nu[2][PDEG + 1];
    __shared__ int   s_iu[2];

    knots_to_sK(knot_u + b * PL, sK, tid);

    if (tid < 2) {
        float Ni[PDEG + 1];
        const int span = basis_at(sK, u[ug * 2 + tid], Ni);
        s_iu[tid] = span - PDEG;
        #pragma unroll
        for (int p = 0; p <= PDEG; p++) s_nu[tid][p] = Ni[p];
    }
    __syncthreads();

    const int uu = ug * 2 + threadIdx.y;
    const int vv = threadIdx.x;
    const int iu = s_iu[threadIdx.y];
    float nu[PDEG + 1];
    #pragma unroll
    for (int p = 0; p <= PDEG; p++) nu[p] = s_nu[threadIdx.y][p];

    const float4* Rb = &g_R[b][iu][0];

    float a0 = 0.0f, a1 = 0.0f, a2 = 0.0f;
    #pragma unroll
    for (int p = 0; p <= PDEG; p++) {
        float4 r = __ldg(&Rb[p * PS + vv]);
        const float w = nu[p];
        a0 = fmaf(w, r.x, a0);
        a1 = fmaf(w, r.y, a1);
        a2 = fmaf(w, r.z, a2);
    }

    float* o = out + (((long)b * PS + uu) * PS + vv) * PDIM;
    o[0] = a0;
    o[1] = a1;
    o[2] = a2;
}

// ---------------------------------------------------------------------------
extern "C" void kernel_launch(void* const* d_in, const int* in_sizes, int n_in,
                              void* d_out, int out_size)
{
    const float* ctrl   = (const float*)d_in[0];  // (B, 128, 128, 3)
    const float* knot_u = (const float*)d_in[1];  // (B, 132)
    const float* knot_v = (const float*)d_in[2];  // (B, 132)
    const float* u      = (const float*)d_in[3];  // (256,)
    const float* v      = (const float*)d_in[4];  // (256,)
    float* out = (float*)d_out;                   // (B, 256, 256, 3)

    surf_rowsum_kernel<<<PB * (PNC / RG), PS>>>(ctrl, knot_v, v);
    dim3 blk(PS, 2);
    surf_ucontract_kernel<<<PB * (PS / 2), blk>>>(knot_u, u, out);
}